// round 7
// baseline (speedup 1.0000x reference)
#include <cuda_runtime.h>

#define W 512
#define H 512
#define NPLANES 96
#define ROWS_PER_SLAB 32
#define SLABS 16           // 16*32 = 512 >= 506
#define TPB 64             // 2 warps; thread owns 8 columns; warps fully decoupled
#define NBLK (NPLANES * SLABS)

typedef unsigned long long u64;

__device__ float    g_part[NBLK];
__device__ unsigned g_count = 0;   // self-resetting; safe across graph replays

// ---- packed f32x2 helpers (ptxas never auto-fuses these) ----
__device__ __forceinline__ u64 pk(float lo, float hi) {
    u64 r; asm("mov.b64 %0, {%1, %2};" : "=l"(r) : "f"(lo), "f"(hi)); return r;
}
__device__ __forceinline__ void upk(u64 v, float& lo, float& hi) {
    asm("mov.b64 {%0, %1}, %2;" : "=f"(lo), "=f"(hi) : "l"(v));
}
__device__ __forceinline__ u64 add2(u64 a, u64 b) {
    u64 r; asm("add.rn.f32x2 %0, %1, %2;" : "=l"(r) : "l"(a), "l"(b)); return r;
}
__device__ __forceinline__ u64 mul2(u64 a, u64 b) {
    u64 r; asm("mul.rn.f32x2 %0, %1, %2;" : "=l"(r) : "l"(a), "l"(b)); return r;
}
__device__ __forceinline__ u64 fma2(u64 a, u64 b, u64 c) {
    u64 r; asm("fma.rn.f32x2 %0, %1, %2, %3;" : "=l"(r) : "l"(a), "l"(b), "l"(c)); return r;
}

__global__ __launch_bounds__(TPB, 8) void ssim_main(const float* __restrict__ g1,
                                                    const float* __restrict__ g2,
                                                    float* __restrict__ out) {
    __shared__ float  wsum[2];
    __shared__ bool   isLast;
    __shared__ double dsum[TPB];

    const int t     = threadIdx.x;
    const int lane  = t & 31;
    const int bid   = blockIdx.x;
    const int plane = bid / SLABS;
    const int slab  = bid % SLABS;
    const int y0    = 3 + slab * ROWS_PER_SLAB;
    const int y1    = min(y0 + ROWS_PER_SLAB - 1, 508);
    const int xb    = t * 8;                 // 8 columns per thread

    const float* p1 = g1 + (size_t)plane * (W * H);
    const float* p2 = g2 + (size_t)plane * (W * H);

    // Vertical running sums over rows y-3..y+3: 4 quantities x 4 col-pairs.
    // q: 0=Sx, 1=Sy, 2=Sxx+Syy, 3=Sxy
    u64 V[4][4];
    #pragma unroll
    for (int q = 0; q < 4; q++)
        #pragma unroll
        for (int j = 0; j < 4; j++) V[q][j] = 0;

    // Redundant seam state (replaces smem exchange + per-row barrier):
    //  t==31 keeps vertical sums of cols 256..258 (VR)
    //  t==32 keeps vertical sums of cols 253..255 (VL)
    float VR[4][3], VL[4][3];
    #pragma unroll
    for (int q = 0; q < 4; q++) { VR[q][0]=VR[q][1]=VR[q][2]=0.f; VL[q][0]=VL[q][1]=VL[q][2]=0.f; }

    #pragma unroll
    for (int j = -3; j <= 3; j++) {
        const float* r1 = p1 + (y0 + j) * W + xb;
        const float* r2 = p2 + (y0 + j) * W + xb;
        float4 A0 = *(const float4*)r1,  A1 = *(const float4*)(r1 + 4);
        float4 B0 = *(const float4*)r2,  B1 = *(const float4*)(r2 + 4);
        u64 a[4] = {pk(A0.x, A0.y), pk(A0.z, A0.w), pk(A1.x, A1.y), pk(A1.z, A1.w)};
        u64 b[4] = {pk(B0.x, B0.y), pk(B0.z, B0.w), pk(B1.x, B1.y), pk(B1.z, B1.w)};
        #pragma unroll
        for (int jj = 0; jj < 4; jj++) {
            V[0][jj] = add2(V[0][jj], a[jj]);
            V[1][jj] = add2(V[1][jj], b[jj]);
            V[2][jj] = fma2(a[jj], a[jj], fma2(b[jj], b[jj], V[2][jj]));
            V[3][jj] = fma2(a[jj], b[jj], V[3][jj]);
        }
        if (t == 31) {
            float4 h1 = *(const float4*)(p1 + (y0 + j) * W + 256);
            float4 h2 = *(const float4*)(p2 + (y0 + j) * W + 256);
            float ha[3] = {h1.x, h1.y, h1.z}, hb[3] = {h2.x, h2.y, h2.z};
            #pragma unroll
            for (int c = 0; c < 3; c++) {
                VR[0][c] += ha[c];
                VR[1][c] += hb[c];
                VR[2][c] = fmaf(ha[c], ha[c], fmaf(hb[c], hb[c], VR[2][c]));
                VR[3][c] = fmaf(ha[c], hb[c], VR[3][c]);
            }
        }
        if (t == 32) {
            float4 h1 = *(const float4*)(p1 + (y0 + j) * W + 252);
            float4 h2 = *(const float4*)(p2 + (y0 + j) * W + 252);
            float ha[3] = {h1.y, h1.z, h1.w}, hb[3] = {h2.y, h2.z, h2.w};
            #pragma unroll
            for (int c = 0; c < 3; c++) {
                VL[0][c] += ha[c];
                VL[1][c] += hb[c];
                VL[2][c] = fmaf(ha[c], ha[c], fmaf(hb[c], hb[c], VL[2][c]));
                VL[3][c] = fmaf(ha[c], hb[c], VL[3][c]);
            }
        }
    }

    // Unnormalized-sum constants (49^2 folded in; ratio invariant).
    const float c1s = 0.2401f, c2s = 2.1609f;
    const float CN  = 49.0f / 48.0f;
    const u64 M1   = pk(-1.f, -1.f);
    const u64 TWO2 = pk(2.f, 2.f);
    const u64 C1v  = pk(c1s, c1s);
    const u64 C2v  = pk(c2s, c2s);
    const u64 MK2v = pk(-2.f * CN, -2.f * CN);
    const u64 FKv  = pk(98.f * CN, 98.f * CN);
    const u64 MCNv = pk(-CN, -CN);
    const u64 M49v = pk(49.f * CN, 49.f * CN);

    float acc = 0.f;

    for (int y = y0;; y++) {
        const bool more = (y < y1);

        // ---- software-pipelined slide loads: issue now, consume after map ----
        float4 A0, A1, B0, B1, C0, C1f, D0, D1;
        float4 hn1, hn2, ho1, ho2;
        if (more) {
            const float* rn1 = p1 + (y + 4) * W + xb;
            const float* rn2 = p2 + (y + 4) * W + xb;
            const float* ro1 = p1 + (y - 3) * W + xb;
            const float* ro2 = p2 + (y - 3) * W + xb;
            A0 = *(const float4*)rn1;  A1  = *(const float4*)(rn1 + 4);
            B0 = *(const float4*)rn2;  B1  = *(const float4*)(rn2 + 4);
            C0 = *(const float4*)ro1;  C1f = *(const float4*)(ro1 + 4);
            D0 = *(const float4*)ro2;  D1  = *(const float4*)(ro2 + 4);
        }
        if (t == 31 && more) {
            hn1 = *(const float4*)(p1 + (y + 4) * W + 256);
            hn2 = *(const float4*)(p2 + (y + 4) * W + 256);
            ho1 = *(const float4*)(p1 + (y - 3) * W + 256);
            ho2 = *(const float4*)(p2 + (y - 3) * W + 256);
        }
        if (t == 32 && more) {
            hn1 = *(const float4*)(p1 + (y + 4) * W + 252);
            hn2 = *(const float4*)(p2 + (y + 4) * W + 252);
            ho1 = *(const float4*)(p1 + (y - 3) * W + 252);
            ho2 = *(const float4*)(p2 + (y - 3) * W + 252);
        }

        // ---- horizontal 7-window sums via prefix + shuffles (no barrier) ----
        u64 Wq[4][4];
        #pragma unroll
        for (int q = 0; q < 4; q++) {
            float v0, v1, v2, v3, v4, v5, v6, v7;
            upk(V[q][0], v0, v1); upk(V[q][1], v2, v3);
            upk(V[q][2], v4, v5); upk(V[q][3], v6, v7);
            float f0 = v0;
            float f1 = f0 + v1, f2 = f1 + v2, f3 = f2 + v3;
            float f4 = f3 + v4, f5 = f4 + v5, f6 = f5 + v6, f7 = f6 + v7;
            float s1 = f7 - f4, s2 = f7 - f5, s3 = f7 - f6;

            float sL1 = __shfl_up_sync(0xffffffffu, s1, 1);
            float sL2 = __shfl_up_sync(0xffffffffu, s2, 1);
            float sL3 = __shfl_up_sync(0xffffffffu, s3, 1);
            float pR0 = __shfl_down_sync(0xffffffffu, f0, 1);
            float pR1 = __shfl_down_sync(0xffffffffu, f1, 1);
            float pR2 = __shfl_down_sync(0xffffffffu, f2, 1);
            if (lane == 0 && t != 0) {           // t=32: left halo from VL regs
                sL3 = VL[q][2];
                sL2 = VL[q][1] + VL[q][2];
                sL1 = VL[q][0] + sL2;
            }
            if (lane == 31 && t != TPB - 1) {    // t=31: right halo from VR regs
                pR0 = VR[q][0];
                pR1 = VR[q][0] + VR[q][1];
                pR2 = pR1 + VR[q][2];
            }
            float w0 = sL1 + f3;
            float w1 = sL2 + f4;
            float w2 = sL3 + f5;
            float w3 = f6;
            float w4 = f7 - f0;
            float w5 = (f7 - f1) + pR0;
            float w6 = (f7 - f2) + pR1;
            float w7 = (f7 - f3) + pR2;
            Wq[q][0] = pk(w0, w1); Wq[q][1] = pk(w2, w3);
            Wq[q][2] = pk(w4, w5); Wq[q][3] = pk(w6, w7);
        }

        // ---- packed SSIM map ----
        float v[8];
        #pragma unroll
        for (int p = 0; p < 4; p++) {
            u64 sx = Wq[0][p], sy = Wq[1][p], sw = Wq[2][p], sp = Wq[3][p];
            u64 P  = mul2(sx, sy);
            u64 r  = fma2(sx, sx, mul2(sy, sy));
            u64 A1v = fma2(P, TWO2, C1v);
            u64 A2v = fma2(MK2v, P, fma2(sp, FKv, C2v));
            u64 B1v = add2(r, C1v);
            u64 B2v = fma2(MCNv, r, fma2(sw, M49v, C2v));
            u64 nm = mul2(A1v, A2v), dn = mul2(B1v, B2v);
            float n0, n1, d0, d1;
            upk(nm, n0, n1); upk(dn, d0, d1);
            v[2 * p]     = __fdividef(n0, d0);
            v[2 * p + 1] = __fdividef(n1, d1);
        }
        // interior columns are 3..508: t=0 drops k<3, t=63 drops k>4
        if (t == 0)            acc += ((v[3] + v[4]) + (v[5] + v[6])) + v[7];
        else if (t == TPB - 1) acc += ((v[0] + v[1]) + (v[2] + v[3])) + v[4];
        else                   acc += ((v[0] + v[1]) + (v[2] + v[3]))
                                    + ((v[4] + v[5]) + (v[6] + v[7]));

        if (!more) break;

        // ---- apply slide update from prefetched rows ----
        u64 a[4]  = {pk(A0.x, A0.y), pk(A0.z, A0.w), pk(A1.x, A1.y), pk(A1.z, A1.w)};
        u64 b[4]  = {pk(B0.x, B0.y), pk(B0.z, B0.w), pk(B1.x, B1.y), pk(B1.z, B1.w)};
        u64 ao[4] = {pk(C0.x, C0.y), pk(C0.z, C0.w), pk(C1f.x, C1f.y), pk(C1f.z, C1f.w)};
        u64 bo[4] = {pk(D0.x, D0.y), pk(D0.z, D0.w), pk(D1.x, D1.y), pk(D1.z, D1.w)};
        #pragma unroll
        for (int jj = 0; jj < 4; jj++) {
            u64 na = mul2(ao[jj], M1), nb = mul2(bo[jj], M1);
            V[0][jj] = add2(V[0][jj], add2(a[jj], na));
            V[1][jj] = add2(V[1][jj], add2(b[jj], nb));
            V[2][jj] = fma2(a[jj], a[jj], fma2(b[jj], b[jj],
                        fma2(na, ao[jj], fma2(nb, bo[jj], V[2][jj]))));
            V[3][jj] = fma2(a[jj], b[jj], fma2(na, bo[jj], V[3][jj]));
        }
        if (t == 31) {
            float ha[3] = {hn1.x, hn1.y, hn1.z}, hb[3] = {hn2.x, hn2.y, hn2.z};
            float oa[3] = {ho1.x, ho1.y, ho1.z}, ob[3] = {ho2.x, ho2.y, ho2.z};
            #pragma unroll
            for (int c = 0; c < 3; c++) {
                VR[0][c] += ha[c] - oa[c];
                VR[1][c] += hb[c] - ob[c];
                VR[2][c] = fmaf(ha[c], ha[c], fmaf(hb[c], hb[c],
                           fmaf(-oa[c], oa[c], fmaf(-ob[c], ob[c], VR[2][c]))));
                VR[3][c] = fmaf(ha[c], hb[c], fmaf(-oa[c], ob[c], VR[3][c]));
            }
        }
        if (t == 32) {
            float ha[3] = {hn1.y, hn1.z, hn1.w}, hb[3] = {hn2.y, hn2.z, hn2.w};
            float oa[3] = {ho1.y, ho1.z, ho1.w}, ob[3] = {ho2.y, ho2.z, ho2.w};
            #pragma unroll
            for (int c = 0; c < 3; c++) {
                VL[0][c] += ha[c] - oa[c];
                VL[1][c] += hb[c] - ob[c];
                VL[2][c] = fmaf(ha[c], ha[c], fmaf(hb[c], hb[c],
                           fmaf(-oa[c], oa[c], fmaf(-ob[c], ob[c], VL[2][c]))));
                VL[3][c] = fmaf(ha[c], hb[c], fmaf(-oa[c], ob[c], VL[3][c]));
            }
        }
    }

    // Block reduction (deterministic)
    #pragma unroll
    for (int off = 16; off; off >>= 1)
        acc += __shfl_down_sync(0xffffffffu, acc, off);
    if (lane == 0) wsum[t >> 5] = acc;
    __syncthreads();

    if (t == 0) {
        g_part[bid] = wsum[0] + wsum[1];
        __threadfence();
        unsigned old = atomicAdd(&g_count, 1u);
        isLast = (old == NBLK - 1);
    }
    __syncthreads();

    // Last block reduces all partials (fixed order -> deterministic)
    if (isLast) {
        __threadfence();
        double s = 0.0;
        for (int i = t; i < NBLK; i += TPB) s += (double)g_part[i];
        dsum[t] = s;
        __syncthreads();
        #pragma unroll
        for (int o = TPB / 2; o > 0; o >>= 1) {
            if (t < o) dsum[t] += dsum[t + o];
            __syncthreads();
        }
        if (t == 0) {
            out[0] = (float)(dsum[0] * (1.0 / (96.0 * 506.0 * 506.0)));
            g_count = 0;   // reset for next graph replay
        }
    }
}

extern "C" void kernel_launch(void* const* d_in, const int* in_sizes, int n_in,
                              void* d_out, int out_size) {
    (void)in_sizes; (void)n_in; (void)out_size;
    const float* img1 = (const float*)d_in[0];
    const float* img2 = (const float*)d_in[1];
    ssim_main<<<NBLK, TPB>>>(img1, img2, (float*)d_out);
}

// round 8
// speedup vs baseline: 1.5723x; 1.5723x over previous
#include <cuda_runtime.h>

#define W 512
#define H 512
#define NPLANES 96
#define ROWS_PER_SLAB 32
#define SLABS 16           // 16*32 = 512 >= 506
#define TPB 64             // 2 warps; thread owns 8 columns
#define NBLK (NPLANES * SLABS)

typedef unsigned long long u64;

__device__ float    g_part[NBLK];
__device__ unsigned g_count = 0;   // self-resetting; safe across graph replays

// ---- packed f32x2 helpers (ptxas never auto-fuses these) ----
__device__ __forceinline__ u64 pk(float lo, float hi) {
    u64 r; asm("mov.b64 %0, {%1, %2};" : "=l"(r) : "f"(lo), "f"(hi)); return r;
}
__device__ __forceinline__ void upk(u64 v, float& lo, float& hi) {
    asm("mov.b64 {%0, %1}, %2;" : "=f"(lo), "=f"(hi) : "l"(v));
}
__device__ __forceinline__ u64 add2(u64 a, u64 b) {
    u64 r; asm("add.rn.f32x2 %0, %1, %2;" : "=l"(r) : "l"(a), "l"(b)); return r;
}
__device__ __forceinline__ u64 mul2(u64 a, u64 b) {
    u64 r; asm("mul.rn.f32x2 %0, %1, %2;" : "=l"(r) : "l"(a), "l"(b)); return r;
}
__device__ __forceinline__ u64 fma2(u64 a, u64 b, u64 c) {
    u64 r; asm("fma.rn.f32x2 %0, %1, %2, %3;" : "=l"(r) : "l"(a), "l"(b), "l"(c)); return r;
}

__global__ __launch_bounds__(TPB, 12) void ssim_main(const float* __restrict__ g1,
                                                     const float* __restrict__ g2,
                                                     float* __restrict__ out) {
    // tiny warp-boundary exchange (double-buffered) + reduction scratch
    __shared__ float  exL[2][4][3];   // written by t=31 (suffix sums), read by t=32
    __shared__ float  exR[2][4][3];   // written by t=32 (prefix sums),  read by t=31
    __shared__ float  wsum[2];
    __shared__ bool   isLast;
    __shared__ double dsum[TPB];

    const int t     = threadIdx.x;
    const int lane  = t & 31;
    const int bid   = blockIdx.x;
    const int plane = bid / SLABS;
    const int slab  = bid % SLABS;
    const int y0    = 3 + slab * ROWS_PER_SLAB;
    const int y1    = min(y0 + ROWS_PER_SLAB - 1, 508);
    const int xb    = t * 8;                 // 8 columns per thread, 32B aligned

    const float* p1 = g1 + (size_t)plane * (W * H);
    const float* p2 = g2 + (size_t)plane * (W * H);

    // Vertical running sums over rows y-3..y+3: 4 quantities x 4 col-pairs.
    // q: 0=Sx, 1=Sy, 2=Sxx+Syy, 3=Sxy
    u64 V[4][4];
    #pragma unroll
    for (int q = 0; q < 4; q++)
        #pragma unroll
        for (int j = 0; j < 4; j++) V[q][j] = 0;

    #pragma unroll
    for (int j = -3; j <= 3; j++) {
        const float* r1 = p1 + (y0 + j) * W + xb;
        const float* r2 = p2 + (y0 + j) * W + xb;
        float4 A0 = *(const float4*)r1,       A1 = *(const float4*)(r1 + 4);
        float4 B0 = *(const float4*)r2,       B1 = *(const float4*)(r2 + 4);
        u64 a[4] = {pk(A0.x, A0.y), pk(A0.z, A0.w), pk(A1.x, A1.y), pk(A1.z, A1.w)};
        u64 b[4] = {pk(B0.x, B0.y), pk(B0.z, B0.w), pk(B1.x, B1.y), pk(B1.z, B1.w)};
        #pragma unroll
        for (int jj = 0; jj < 4; jj++) {
            V[0][jj] = add2(V[0][jj], a[jj]);
            V[1][jj] = add2(V[1][jj], b[jj]);
            V[2][jj] = fma2(a[jj], a[jj], fma2(b[jj], b[jj], V[2][jj]));
            V[3][jj] = fma2(a[jj], b[jj], V[3][jj]);
        }
    }

    // Unnormalized-sum constants (49^2 folded in; ratio invariant).
    const float c1s = 0.2401f, c2s = 2.1609f;
    const float CN  = 49.0f / 48.0f;
    const u64 M1   = pk(-1.f, -1.f);
    const u64 TWO2 = pk(2.f, 2.f);
    const u64 C1v  = pk(c1s, c1s);
    const u64 C2v  = pk(c2s, c2s);
    const u64 MK2v = pk(-2.f * CN, -2.f * CN);
    const u64 FKv  = pk(98.f * CN, 98.f * CN);
    const u64 MCNv = pk(-CN, -CN);
    const u64 M49v = pk(49.f * CN, 49.f * CN);

    float acc = 0.f;

    for (int y = y0;; y++) {
        const int pb = y & 1;

        // Warp-boundary exchange (col 256): t=31 provides its last-3 suffix
        // sums to t=32; t=32 provides its first-3 prefix sums to t=31.
        if (t == 31) {
            #pragma unroll
            for (int q = 0; q < 4; q++) {
                float v4, v5, v6, v7;
                upk(V[q][2], v4, v5); upk(V[q][3], v6, v7);
                float s3 = v7, s2 = v6 + v7, s1 = v5 + s2;
                exL[pb][q][0] = s1; exL[pb][q][1] = s2; exL[pb][q][2] = s3;
            }
        }
        if (t == 32) {
            #pragma unroll
            for (int q = 0; q < 4; q++) {
                float v0, v1, v2, v3;
                upk(V[q][0], v0, v1); upk(V[q][1], v2, v3);
                exR[pb][q][0] = v0; exR[pb][q][1] = v0 + v1; exR[pb][q][2] = v0 + v1 + v2;
            }
        }
        __syncthreads();

        // Horizontal 7-window sums for 8 output cols via prefix + shuffles.
        u64 Wq[4][4];
        #pragma unroll
        for (int q = 0; q < 4; q++) {
            float v0, v1, v2, v3, v4, v5, v6, v7;
            upk(V[q][0], v0, v1); upk(V[q][1], v2, v3);
            upk(V[q][2], v4, v5); upk(V[q][3], v6, v7);
            float f0 = v0;
            float f1 = f0 + v1, f2 = f1 + v2, f3 = f2 + v3;
            float f4 = f3 + v4, f5 = f4 + v5, f6 = f5 + v6, f7 = f6 + v7;
            float s1 = f7 - f4, s2 = f7 - f5, s3 = f7 - f6;

            float sL1 = __shfl_up_sync(0xffffffffu, s1, 1);
            float sL2 = __shfl_up_sync(0xffffffffu, s2, 1);
            float sL3 = __shfl_up_sync(0xffffffffu, s3, 1);
            float pR0 = __shfl_down_sync(0xffffffffu, f0, 1);
            float pR1 = __shfl_down_sync(0xffffffffu, f1, 1);
            float pR2 = __shfl_down_sync(0xffffffffu, f2, 1);
            if (lane == 0 && t != 0) {           // t=32: real left halo from t=31
                sL1 = exL[pb][q][0]; sL2 = exL[pb][q][1]; sL3 = exL[pb][q][2];
            }
            if (lane == 31 && t != TPB - 1) {    // t=31: real right halo from t=32
                pR0 = exR[pb][q][0]; pR1 = exR[pb][q][1]; pR2 = exR[pb][q][2];
            }
            float w0 = sL1 + f3;
            float w1 = sL2 + f4;
            float w2 = sL3 + f5;
            float w3 = f6;
            float w4 = f7 - f0;
            float w5 = (f7 - f1) + pR0;
            float w6 = (f7 - f2) + pR1;
            float w7 = (f7 - f3) + pR2;
            Wq[q][0] = pk(w0, w1); Wq[q][1] = pk(w2, w3);
            Wq[q][2] = pk(w4, w5); Wq[q][3] = pk(w6, w7);
        }

        // Packed SSIM map for 4 col-pairs.
        float v[8];
        #pragma unroll
        for (int p = 0; p < 4; p++) {
            u64 sx = Wq[0][p], sy = Wq[1][p], sw = Wq[2][p], sp = Wq[3][p];
            u64 P  = mul2(sx, sy);
            u64 r  = fma2(sx, sx, mul2(sy, sy));
            u64 A1v = fma2(P, TWO2, C1v);
            u64 A2v = fma2(MK2v, P, fma2(sp, FKv, C2v));
            u64 B1v = add2(r, C1v);
            u64 B2v = fma2(MCNv, r, fma2(sw, M49v, C2v));
            u64 nm = mul2(A1v, A2v), dn = mul2(B1v, B2v);
            float n0, n1, d0, d1;
            upk(nm, n0, n1); upk(dn, d0, d1);
            v[2 * p]     = __fdividef(n0, d0);
            v[2 * p + 1] = __fdividef(n1, d1);
        }
        // interior columns are 3..508: t=0 drops k<3, t=63 drops k>4
        if (t == 0)            acc += ((v[3] + v[4]) + (v[5] + v[6])) + v[7];
        else if (t == TPB - 1) acc += ((v[0] + v[1]) + (v[2] + v[3])) + v[4];
        else                   acc += ((v[0] + v[1]) + (v[2] + v[3]))
                                    + ((v[4] + v[5]) + (v[6] + v[7]));

        if (y >= y1) break;

        // Slide vertical sums: add row y+4, subtract row y-3 (re-read, hot in cache)
        const float* rn1 = p1 + (y + 4) * W + xb;
        const float* rn2 = p2 + (y + 4) * W + xb;
        const float* ro1 = p1 + (y - 3) * W + xb;
        const float* ro2 = p2 + (y - 3) * W + xb;
        float4 A0 = *(const float4*)rn1,  A1 = *(const float4*)(rn1 + 4);
        float4 B0 = *(const float4*)rn2,  B1 = *(const float4*)(rn2 + 4);
        float4 C0 = *(const float4*)ro1,  C1f = *(const float4*)(ro1 + 4);
        float4 D0 = *(const float4*)ro2,  D1 = *(const float4*)(ro2 + 4);
        u64 a[4]  = {pk(A0.x, A0.y), pk(A0.z, A0.w), pk(A1.x, A1.y), pk(A1.z, A1.w)};
        u64 b[4]  = {pk(B0.x, B0.y), pk(B0.z, B0.w), pk(B1.x, B1.y), pk(B1.z, B1.w)};
        u64 ao[4] = {pk(C0.x, C0.y), pk(C0.z, C0.w), pk(C1f.x, C1f.y), pk(C1f.z, C1f.w)};
        u64 bo[4] = {pk(D0.x, D0.y), pk(D0.z, D0.w), pk(D1.x, D1.y), pk(D1.z, D1.w)};
        #pragma unroll
        for (int jj = 0; jj < 4; jj++) {
            u64 na = mul2(ao[jj], M1), nb = mul2(bo[jj], M1);
            V[0][jj] = add2(V[0][jj], add2(a[jj], na));
            V[1][jj] = add2(V[1][jj], add2(b[jj], nb));
            V[2][jj] = fma2(a[jj], a[jj], fma2(b[jj], b[jj],
                        fma2(na, ao[jj], fma2(nb, bo[jj], V[2][jj]))));
            V[3][jj] = fma2(a[jj], b[jj], fma2(na, bo[jj], V[3][jj]));
        }
    }

    // Block reduction (deterministic)
    #pragma unroll
    for (int off = 16; off; off >>= 1)
        acc += __shfl_down_sync(0xffffffffu, acc, off);
    if (lane == 0) wsum[t >> 5] = acc;
    __syncthreads();

    if (t == 0) {
        g_part[bid] = wsum[0] + wsum[1];
        __threadfence();
        unsigned old = atomicAdd(&g_count, 1u);
        isLast = (old == NBLK - 1);
    }
    __syncthreads();

    // Last block reduces all partials (fixed order -> deterministic)
    if (isLast) {
        __threadfence();
        double s = 0.0;
        for (int i = t; i < NBLK; i += TPB) s += (double)g_part[i];
        dsum[t] = s;
        __syncthreads();
        #pragma unroll
        for (int o = TPB / 2; o > 0; o >>= 1) {
            if (t < o) dsum[t] += dsum[t + o];
            __syncthreads();
        }
        if (t == 0) {
            out[0] = (float)(dsum[0] * (1.0 / (96.0 * 506.0 * 506.0)));
            g_count = 0;   // reset for next graph replay
        }
    }
}

extern "C" void kernel_launch(void* const* d_in, const int* in_sizes, int n_in,
                              void* d_out, int out_size) {
    (void)in_sizes; (void)n_in; (void)out_size;
    const float* img1 = (const float*)d_in[0];
    const float* img2 = (const float*)d_in[1];
    ssim_main<<<NBLK, TPB>>>(img1, img2, (float*)d_out);
}